// round 6
// baseline (speedup 1.0000x reference)
#include <cuda_runtime.h>
#include <cuda_bf16.h>
#include <cstddef>

// B=32, H=W=64, C=64, K=3, S=1, PAD=1; Hp=Wp=66, OUT=192. Pure gather:
//   out[b,c2,r,s] = up_flat[c2*4356 + ip*66 + jp], ip=r/3+r%3, jp=s/3+s%3
//   up_flat[t]: p=t>>6, c=t&63, rp=p/66, cp=p%66;
//   interior -> in[b, (p-2rp-65), c] else 0.
// 1024 blocks (single resident wave @ ~7 blocks/SM), each handles windows
// w and w+1024, where window w -> (b = w>>6, c2 = w&63).
#define HP      66
#define NP      (HP * HP)        // 4356 floats per window
#define OUT     192
#define NWIN    2048
#define GRID    1024

__global__ __launch_bounds__(192)
void padding_jacobians_kernel(const float* __restrict__ in,
                              float* __restrict__ out) {
    __shared__ float sm[NP];               // 17424 B

    const int tx  = threadIdx.x;           // 0..47  (s-quad index)
    const int ty  = threadIdx.y;           // 0..3
    const int tid = ty * 48 + tx;

    // store-phase per-thread constants (window-independent)
    const int s0 = 4 * tx;
    const int jp0 =  s0      / 3 +  s0      % 3;
    const int jp1 = (s0 + 1) / 3 + (s0 + 1) % 3;
    const int jp2 = (s0 + 2) / 3 + (s0 + 2) % 3;
    const int jp3 = (s0 + 3) / 3 + (s0 + 3) % 3;

    #pragma unroll 1
    for (int wi = 0; wi < NWIN / GRID; ++wi) {
        const unsigned w  = blockIdx.x + (unsigned)wi * GRID;
        const unsigned c2 = w & 63u;
        const unsigned b  = w >> 6;

        const float* __restrict__ inb = in + (size_t)b * (64 * 64 * 64);
        const unsigned base_t = c2 * NP;   // multiple of 4

        // ---- Load phase: sm[i] = up_flat[base_t + i] (zero on border).
        // float4 granules never cross a p boundary (t%4==0, 4|64).
        #pragma unroll 1
        for (unsigned q = tid; q < NP / 4; q += 192) {
            unsigned t  = base_t + 4u * q;
            unsigned p  = t >> 6;
            unsigned c  = t & 63u;
            unsigned rp = (p * 993u) >> 16;    // == p/66 for p < 4356 (exact)
            unsigned cp = p - 66u * rp;
            float4 v = make_float4(0.f, 0.f, 0.f, 0.f);
            if ((rp - 1u) < 64u && (cp - 1u) < 64u) {
                v = *reinterpret_cast<const float4*>(
                        inb + ((p - 2u * rp - 65u) << 6) + c);
            }
            reinterpret_cast<float4*>(sm)[q] = v;
        }
        __syncthreads();

        // ---- Store phase: expand window to 192x192 tile, coalesced float4.
        float* __restrict__ outp =
            out + (size_t)(b * 64 + c2) * (OUT * OUT) + s0;

        int o = ty / 3;      // r/3 for r=ty
        int k = ty % 3;      // r%3
        #pragma unroll 4
        for (int r = ty; r < OUT; r += 4) {
            const float* row = sm + (o + k) * HP;   // ip = o + k
            float4 v = make_float4(row[jp0], row[jp1], row[jp2], row[jp3]);
            *reinterpret_cast<float4*>(outp + (size_t)r * OUT) = v;
            o += (k < 2) ? 1 : 2;                   // (r+4)/3
            k = (k == 2) ? 0 : (k + 1);             // (r+4)%3
        }
        __syncthreads();   // protect sm before next window's load
    }
}

extern "C" void kernel_launch(void* const* d_in, const int* in_sizes, int n_in,
                              void* d_out, int out_size) {
    const float* in  = (const float*)d_in[0];
    float*       out = (float*)d_out;
    (void)in_sizes; (void)n_in; (void)out_size;

    dim3 block(48, 4);        // 192 threads
    padding_jacobians_kernel<<<GRID, block>>>(in, out);
}

// round 7
// speedup vs baseline: 1.1185x; 1.1185x over previous
#include <cuda_runtime.h>
#include <cuda_bf16.h>
#include <cstddef>

// B=32, H=W=64, C=64, K=3, S=1, PAD=1; Hp=Wp=66, OUT=192. Pure gather:
//   out[b,c2,r,s] = up_flat[c2*4356 + ip*66 + jp], ip=r/3+r%3, jp=s/3+s%3
//   up_flat[t]: p=t>>6, c=t&63, rp=p/66, cp=p%66;
//   interior -> in[b, (p-2rp-65), c] else 0.
// R3 structure + streaming cache hints (__ldcs/__stcs) + 384-thread blocks.
#define HP      66
#define NP      (HP * HP)        // 4356 floats per (b,c2) window
#define OUT     192
#define BATCH   32

__global__ __launch_bounds__(384)
void padding_jacobians_kernel(const float* __restrict__ in,
                              float* __restrict__ out) {
    __shared__ float sm[NP];               // 17424 B

    const unsigned c2 = blockIdx.x;        // 0..63
    const unsigned b  = blockIdx.y;        // 0..31
    const int tx  = threadIdx.x;           // 0..47  (s-quad index)
    const int ty  = threadIdx.y;           // 0..7
    const int tid = ty * 48 + tx;

    const float* __restrict__ inb = in + (size_t)b * (64 * 64 * 64);
    const unsigned base_t = c2 * NP;       // multiple of 4

    // ---- Load phase: sm[i] = up_flat[base_t + i] (zero on padded border).
    // float4 granules never cross a p boundary (t%4==0, 4|64). 1089 float4s.
    #pragma unroll 1
    for (unsigned q = tid; q < NP / 4; q += 384) {
        unsigned t  = base_t + 4u * q;
        unsigned p  = t >> 6;
        unsigned c  = t & 63u;
        unsigned rp = (p * 993u) >> 16;    // == p/66 for p < 4356 (exact)
        unsigned cp = p - 66u * rp;
        float4 v = make_float4(0.f, 0.f, 0.f, 0.f);
        if ((rp - 1u) < 64u && (cp - 1u) < 64u) {
            v = __ldcs(reinterpret_cast<const float4*>(
                    inb + ((p - 2u * rp - 65u) << 6) + c));   // read-once
        }
        reinterpret_cast<float4*>(sm)[q] = v;
    }
    __syncthreads();

    // ---- Store phase: expand window to 192x192 tile, coalesced streaming
    // float4 stores. Thread (tx,ty) writes rows r = ty+8*it, cols 4tx..4tx+3.
    const int s0 = 4 * tx;
    const int jp0 =  s0      / 3 +  s0      % 3;
    const int jp1 = (s0 + 1) / 3 + (s0 + 1) % 3;
    const int jp2 = (s0 + 2) / 3 + (s0 + 2) % 3;
    const int jp3 = (s0 + 3) / 3 + (s0 + 3) % 3;

    float* __restrict__ outp =
        out + (size_t)(b * 64 + c2) * (OUT * OUT) + (size_t)ty * OUT + s0;

    // maintain o = r/3, k = r%3 as r steps by 8:
    //   k'=(k+2)%3;  o += (k==0) ? 2 : 3
    int o = ty / 3;          // ty in 0..7
    int k = ty % 3;
    #pragma unroll 4
    for (int it = 0; it < OUT / 8; ++it) {
        const float* row = sm + (o + k) * HP;   // ip = o + k
        float4 v = make_float4(row[jp0], row[jp1], row[jp2], row[jp3]);
        __stcs(reinterpret_cast<float4*>(outp), v);   // write-once, evict-first
        outp += (size_t)8 * OUT;
        o += (k == 0) ? 2 : 3;
        k = (k == 2) ? 1 : ((k == 1) ? 0 : 2);        // (k+2)%3
    }
}

extern "C" void kernel_launch(void* const* d_in, const int* in_sizes, int n_in,
                              void* d_out, int out_size) {
    const float* in  = (const float*)d_in[0];
    float*       out = (float*)d_out;
    (void)in_sizes; (void)n_in; (void)out_size;

    dim3 grid(64, BATCH);     // (c2, b)
    dim3 block(48, 8);        // 384 threads
    padding_jacobians_kernel<<<grid, block>>>(in, out);
}